// round 2
// baseline (speedup 1.0000x reference)
#include <cuda_runtime.h>
#include <math.h>

#define N_TOK 2048
#define C     128
#define CPD   16
#define H     8
#define HD    16
#define NQ    32
#define NK    128
#define NB    64
#define PADW  48
#define TR    16   // rows per GEMM block

// Scratch (device globals — no allocations allowed)
__device__ float g_q  [N_TOK * C];
__device__ float g_k  [N_TOK * C];
__device__ float g_v  [N_TOK * C];
__device__ float g_o  [N_TOK * C];
__device__ float g_pb [NB * H * NQ * NK];   // pair bias, layout [i][h][q][k]

__device__ __forceinline__ float sigmoidf_(float x) {
    return 1.0f / (1.0f + __expf(-x));
}

// ---------------------------------------------------------------------------
// Kernel 1 (fused): per 16-row tile:
//   lnx = LN(x); sn = LN(s)*sw
//   a   = sigmoid(sn@Wg + bg)*lnx + sn@Ws
//   q   = a@Wq + bq ; k = a@Wk ; v = a@Wv
// 128 blocks x 256 threads. Two chained smem GEMM phases.
// ---------------------------------------------------------------------------
__global__ void fused_front_kernel(const float* __restrict__ x,
                                   const float* __restrict__ s,
                                   const float* __restrict__ sw,
                                   const float* __restrict__ Wg,
                                   const float* __restrict__ bg,
                                   const float* __restrict__ Ws,
                                   const float* __restrict__ Wq,
                                   const float* __restrict__ bq,
                                   const float* __restrict__ Wk,
                                   const float* __restrict__ Wv) {
    int row0 = blockIdx.x * TR;
    int t = threadIdx.x;            // 256
    int w = t >> 5, l = t & 31;
    __shared__ float Sn[TR][C];
    __shared__ float Lx[TR][C];
    __shared__ float As[TR][C];

    // --- LN phase: 8 warps, 2 rows each; lane loads float4 (128 = 32*4) ---
    #pragma unroll
    for (int rr_ = 0; rr_ < 2; rr_++) {
        int r = w * 2 + rr_;
        float4 xv = ((const float4*)(x + (size_t)(row0 + r) * C))[l];
        float4 sv = ((const float4*)(s + (size_t)(row0 + r) * C))[l];
        float sx  = xv.x + xv.y + xv.z + xv.w;
        float sxx = xv.x*xv.x + xv.y*xv.y + xv.z*xv.z + xv.w*xv.w;
        float ss  = sv.x + sv.y + sv.z + sv.w;
        float sss = sv.x*sv.x + sv.y*sv.y + sv.z*sv.z + sv.w*sv.w;
        #pragma unroll
        for (int o = 16; o > 0; o >>= 1) {
            sx  += __shfl_xor_sync(0xffffffffu, sx,  o);
            sxx += __shfl_xor_sync(0xffffffffu, sxx, o);
            ss  += __shfl_xor_sync(0xffffffffu, ss,  o);
            sss += __shfl_xor_sync(0xffffffffu, sss, o);
        }
        float mx = sx * (1.0f / C);
        float vx = sxx * (1.0f / C) - mx * mx;
        float ms = ss * (1.0f / C);
        float vs = sss * (1.0f / C) - ms * ms;
        float rx = rsqrtf(vx + 1e-5f);
        float rs = rsqrtf(vs + 1e-5f);
        int col = l * 4;
        float4 swv = ((const float4*)sw)[l];
        Lx[r][col + 0] = (xv.x - mx) * rx;
        Lx[r][col + 1] = (xv.y - mx) * rx;
        Lx[r][col + 2] = (xv.z - mx) * rx;
        Lx[r][col + 3] = (xv.w - mx) * rx;
        Sn[r][col + 0] = (sv.x - ms) * rs * swv.x;
        Sn[r][col + 1] = (sv.y - ms) * rs * swv.y;
        Sn[r][col + 2] = (sv.z - ms) * rs * swv.z;
        Sn[r][col + 3] = (sv.w - ms) * rs * swv.w;
    }
    __syncthreads();

    int jc = (t & 31) * 4;
    int rr = (t >> 5) * 2;

    // --- phase A: a = sigmoid(sn@Wg+bg)*lnx + sn@Ws ---
    {
        float ag[2][4] = {}, ak[2][4] = {};
        #pragma unroll 4
        for (int c = 0; c < C; c++) {
            float4 wg = *(const float4*)(Wg + c * C + jc);
            float4 ws = *(const float4*)(Ws + c * C + jc);
            #pragma unroll
            for (int r = 0; r < 2; r++) {
                float a0 = Sn[rr + r][c];
                ag[r][0] += a0 * wg.x; ag[r][1] += a0 * wg.y;
                ag[r][2] += a0 * wg.z; ag[r][3] += a0 * wg.w;
                ak[r][0] += a0 * ws.x; ak[r][1] += a0 * ws.y;
                ak[r][2] += a0 * ws.z; ak[r][3] += a0 * ws.w;
            }
        }
        #pragma unroll
        for (int r = 0; r < 2; r++)
            #pragma unroll
            for (int u = 0; u < 4; u++)
                As[rr + r][jc + u] =
                    sigmoidf_(ag[r][u] + bg[jc + u]) * Lx[rr + r][jc + u] + ak[r][u];
    }
    __syncthreads();

    // --- phase B: q/k/v = a @ {Wq,Wk,Wv} ---
    {
        float aq[2][4] = {}, ak[2][4] = {}, av[2][4] = {};
        #pragma unroll 2
        for (int c = 0; c < C; c++) {
            float4 wq = *(const float4*)(Wq + c * C + jc);
            float4 wk = *(const float4*)(Wk + c * C + jc);
            float4 wv = *(const float4*)(Wv + c * C + jc);
            #pragma unroll
            for (int r = 0; r < 2; r++) {
                float a0 = As[rr + r][c];
                aq[r][0] += a0 * wq.x; aq[r][1] += a0 * wq.y;
                aq[r][2] += a0 * wq.z; aq[r][3] += a0 * wq.w;
                ak[r][0] += a0 * wk.x; ak[r][1] += a0 * wk.y;
                ak[r][2] += a0 * wk.z; ak[r][3] += a0 * wk.w;
                av[r][0] += a0 * wv.x; av[r][1] += a0 * wv.y;
                av[r][2] += a0 * wv.z; av[r][3] += a0 * wv.w;
            }
        }
        #pragma unroll
        for (int r = 0; r < 2; r++)
            #pragma unroll
            for (int u = 0; u < 4; u++) {
                int n = row0 + rr + r, j = jc + u;
                g_q[n * C + j] = aq[r][u] + bq[j];
                g_k[n * C + j] = ak[r][u];
                g_v[n * C + j] = av[r][u];
            }
    }
}

// ---------------------------------------------------------------------------
// Kernel 2: windowed pair bias.  Only reads the used 1/16 of `pair` (16 MB).
// bias[i][h][q][k] = (LN(pair[n,m]) * lnw + lnb) @ proj ; 0 for OOB keys.
// One thread per (i,q,k).  Reads & writes fully coalesced.
// ---------------------------------------------------------------------------
__global__ void pbias_kernel(const float* __restrict__ pair,
                             const float* __restrict__ lnw,
                             const float* __restrict__ lnb,
                             const float* __restrict__ proj) {
    int gid = blockIdx.x * blockDim.x + threadIdx.x;  // 0 .. 262143
    int i = gid >> 12;
    int q = (gid >> 7) & 31;
    int k = gid & 127;
    int n = i * NQ + q;
    int m = i * NQ - PADW + k;

    float b[8] = {0, 0, 0, 0, 0, 0, 0, 0};
    if (m >= 0 && m < N_TOK) {
        const float4* p = (const float4*)(pair + ((size_t)n * N_TOK + m) * CPD);
        float4 v0 = p[0], v1 = p[1], v2 = p[2], v3 = p[3];
        float vals[16] = {v0.x, v0.y, v0.z, v0.w, v1.x, v1.y, v1.z, v1.w,
                          v2.x, v2.y, v2.z, v2.w, v3.x, v3.y, v3.z, v3.w};
        float sum = 0.f;
        #pragma unroll
        for (int c = 0; c < 16; c++) sum += vals[c];
        float mean = sum * (1.0f / 16.0f);
        float var = 0.f;
        #pragma unroll
        for (int c = 0; c < 16; c++) {
            float d = vals[c] - mean;
            var += d * d;
        }
        var *= (1.0f / 16.0f);
        float rs = rsqrtf(var + 1e-5f);
        #pragma unroll
        for (int c = 0; c < 16; c++) {
            float y = (vals[c] - mean) * rs * lnw[c] + lnb[c];
            #pragma unroll
            for (int h = 0; h < 8; h++) b[h] += y * proj[c * 8 + h];
        }
    }
    #pragma unroll
    for (int h = 0; h < 8; h++)
        g_pb[((i * H + h) * NQ + q) * NK + k] = b[h];
}

// ---------------------------------------------------------------------------
// Kernel 3: local window attention.  1 block per (head, window) = 512 blocks.
// Smem padded to 17 floats/row -> conflict-free for the kb-strided access.
// Softmax via 8-lane shfl-xor groups; logits live in registers.
// ---------------------------------------------------------------------------
__global__ void attn_kernel() {
    int h = blockIdx.x;
    int i = blockIdx.y;
    int t = threadIdx.x;       // 256
    __shared__ float Ks[NK * 17];
    __shared__ float Vs[NK * 17];
    __shared__ float Qs[NQ * 17];

    int qi = t >> 3;
    int kb = t & 7;
    int base_m = i * NQ - PADW;

    for (int idx = t; idx < NK * HD; idx += 256) {
        int kk = idx >> 4, d = idx & 15;
        int m = base_m + kk;
        float kvv = 0.f, vvv = 0.f;
        if (m >= 0 && m < N_TOK) {
            kvv = g_k[m * C + h * HD + d];
            vvv = g_v[m * C + h * HD + d];
        }
        Ks[kk * 17 + d] = kvv;
        Vs[kk * 17 + d] = vvv;
    }
    for (int idx = t; idx < NQ * HD; idx += 256) {
        int qq = idx >> 4, d = idx & 15;
        Qs[qq * 17 + d] = g_q[(i * NQ + qq) * C + h * HD + d];
    }
    __syncthreads();

    float qr[16];
    #pragma unroll
    for (int d = 0; d < 16; d++) qr[d] = Qs[qi * 17 + d];

    const float* bp = g_pb + ((i * H + h) * NQ + qi) * NK;

    float lg[16];
    #pragma unroll
    for (int j = 0; j < 16; j++) {
        int k = kb + 8 * j;
        float acc = 0.f;
        #pragma unroll
        for (int d = 0; d < 16; d++) acc += qr[d] * Ks[k * 17 + d];
        lg[j] = acc * 0.25f + bp[k];
    }

    float mx = lg[0];
    #pragma unroll
    for (int j = 1; j < 16; j++) mx = fmaxf(mx, lg[j]);
    #pragma unroll
    for (int o = 4; o > 0; o >>= 1)
        mx = fmaxf(mx, __shfl_xor_sync(0xffffffffu, mx, o));

    float sm = 0.f;
    #pragma unroll
    for (int j = 0; j < 16; j++) {
        lg[j] = __expf(lg[j] - mx);
        sm += lg[j];
    }
    #pragma unroll
    for (int o = 4; o > 0; o >>= 1)
        sm += __shfl_xor_sync(0xffffffffu, sm, o);
    float inv = 1.0f / sm;

    float po[16] = {};
    #pragma unroll
    for (int j = 0; j < 16; j++) {
        int k = kb + 8 * j;
        float p = lg[j] * inv;
        #pragma unroll
        for (int d = 0; d < 16; d++) po[d] += p * Vs[k * 17 + d];
    }
    #pragma unroll
    for (int o = 4; o > 0; o >>= 1) {
        #pragma unroll
        for (int d = 0; d < 16; d++)
            po[d] += __shfl_xor_sync(0xffffffffu, po[d], o);
    }
    int n = i * NQ + qi;
    g_o[n * C + h * HD + 2 * kb]     = po[2 * kb];
    g_o[n * C + h * HD + 2 * kb + 1] = po[2 * kb + 1];
}

// ---------------------------------------------------------------------------
// Kernel 4: row-local tail chain, 3 GEMM phases in one block:
//   g = sigmoid(o@Wg)*o ; t1 = g@Wp ; out = sigmoid(t1@Wo + bo)*t1
// 128 blocks x 256 threads, 16 rows per block.
// ---------------------------------------------------------------------------
__global__ void tail_kernel(const float* __restrict__ Wg,
                            const float* __restrict__ Wp,
                            const float* __restrict__ Wo,
                            const float* __restrict__ bo,
                            float* __restrict__ out) {
    int row0 = blockIdx.x * TR;
    int t = threadIdx.x;
    __shared__ float A[TR][C];
    __shared__ float Bm[TR][C];
    for (int idx = t; idx < TR * C; idx += 256)
        A[idx >> 7][idx & 127] = g_o[row0 * C + idx];
    __syncthreads();

    int jc = (t & 31) * 4;
    int rr = (t >> 5) * 2;

    // phase 1: Bm = sigmoid(A@Wg) * A
    {
        float acc[2][4] = {};
        #pragma unroll 4
        for (int c = 0; c < C; c++) {
            float4 wv = *(const float4*)(Wg + c * C + jc);
            #pragma unroll
            for (int r = 0; r < 2; r++) {
                float a0 = A[rr + r][c];
                acc[r][0] += a0 * wv.x; acc[r][1] += a0 * wv.y;
                acc[r][2] += a0 * wv.z; acc[r][3] += a0 * wv.w;
            }
        }
        #pragma unroll
        for (int r = 0; r < 2; r++)
            #pragma unroll
            for (int u = 0; u < 4; u++)
                Bm[rr + r][jc + u] = sigmoidf_(acc[r][u]) * A[rr + r][jc + u];
    }
    __syncthreads();

    // phase 2: A = Bm@Wp (overwrite o tile; all A reads finished)
    {
        float acc[2][4] = {};
        #pragma unroll 4
        for (int c = 0; c < C; c++) {
            float4 wv = *(const float4*)(Wp + c * C + jc);
            #pragma unroll
            for (int r = 0; r < 2; r++) {
                float a0 = Bm[rr + r][c];
                acc[r][0] += a0 * wv.x; acc[r][1] += a0 * wv.y;
                acc[r][2] += a0 * wv.z; acc[r][3] += a0 * wv.w;
            }
        }
        __syncthreads();
        #pragma unroll
        for (int r = 0; r < 2; r++)
            #pragma unroll
            for (int u = 0; u < 4; u++)
                A[rr + r][jc + u] = acc[r][u];
    }
    __syncthreads();

    // phase 3: out = sigmoid(A@Wo + bo) * A
    {
        float acc[2][4] = {};
        #pragma unroll 4
        for (int c = 0; c < C; c++) {
            float4 wv = *(const float4*)(Wo + c * C + jc);
            #pragma unroll
            for (int r = 0; r < 2; r++) {
                float a0 = A[rr + r][c];
                acc[r][0] += a0 * wv.x; acc[r][1] += a0 * wv.y;
                acc[r][2] += a0 * wv.z; acc[r][3] += a0 * wv.w;
            }
        }
        #pragma unroll
        for (int r = 0; r < 2; r++)
            #pragma unroll
            for (int u = 0; u < 4; u++) {
                float tv = acc[r][u] + bo[jc + u];
                out[(row0 + rr + r) * C + jc + u] = sigmoidf_(tv) * A[rr + r][jc + u];
            }
    }
}

// ---------------------------------------------------------------------------
extern "C" void kernel_launch(void* const* d_in, const int* in_sizes, int n_in,
                              void* d_out, int out_size) {
    const float* x        = (const float*)d_in[0];
    const float* s        = (const float*)d_in[1];
    const float* pair     = (const float*)d_in[2];
    const float* adaln_sw = (const float*)d_in[3];
    const float* adaln_gw = (const float*)d_in[4];
    const float* adaln_gb = (const float*)d_in[5];
    const float* adaln_kw = (const float*)d_in[6];
    const float* q_w      = (const float*)d_in[7];
    const float* q_b      = (const float*)d_in[8];
    const float* k_w      = (const float*)d_in[9];
    const float* v_w      = (const float*)d_in[10];
    const float* p_lnw    = (const float*)d_in[11];
    const float* p_lnb    = (const float*)d_in[12];
    const float* p_proj   = (const float*)d_in[13];
    const float* gate_w   = (const float*)d_in[14];
    const float* proj_w   = (const float*)d_in[15];
    const float* out_w    = (const float*)d_in[16];
    const float* out_b    = (const float*)d_in[17];
    float* out = (float*)d_out;

    fused_front_kernel<<<N_TOK / TR, 256>>>(x, s, adaln_sw,
                                            adaln_gw, adaln_gb, adaln_kw,
                                            q_w, q_b, k_w, v_w);
    pbias_kernel<<<(NB * NQ * NK) / 256, 256>>>(pair, p_lnw, p_lnb, p_proj);
    attn_kernel <<<dim3(H, NB), 256>>>();
    tail_kernel <<<N_TOK / TR, 256>>>(gate_w, proj_w, out_w, out_b, out);
}

// round 3
// speedup vs baseline: 1.1339x; 1.1339x over previous
#include <cuda_runtime.h>
#include <math.h>

#define N_TOK 2048
#define C     128
#define CPD   16
#define H     8
#define HD    16
#define NQ    32
#define NK    128
#define NB    64
#define PADW  48
#define TR    16   // rows per GEMM block
#define KT    32   // k-tile rows staged in smem (16KB)

// Scratch (device globals — no allocations allowed)
__device__ float g_q  [N_TOK * C];
__device__ float g_k  [N_TOK * C];
__device__ float g_v  [N_TOK * C];
__device__ float g_o  [N_TOK * C];
__device__ float g_pb [NB * H * NQ * NK];   // pair bias, layout [i][h][q][k]

__device__ __forceinline__ float sigmoidf_(float x) {
    return 1.0f / (1.0f + __expf(-x));
}

// ---------------------------------------------------------------------------
// One GEMM pass: acc[2][4] += In[rr..rr+1][:] @ W[:, jc..jc+3]
// W (128x128 row-major) streamed through a 32x128 smem tile with register
// prefetch of the next tile overlapped with compute.
// Caller guarantees: In is fully written before call and a __syncthreads()
// (this pass's internal prologue sync) orders it; Wt free for reuse on return.
// ---------------------------------------------------------------------------
__device__ __forceinline__ void gemm_pass(const float (*In)[C],
                                          const float* __restrict__ W,
                                          float (*Wt)[C],
                                          float acc[2][4],
                                          int rr, int jc, int t) {
    float4 pre[4];
    const float4* src0 = (const float4*)W;
    #pragma unroll
    for (int u = 0; u < 4; u++) pre[u] = src0[t + u * 256];
    #pragma unroll
    for (int u = 0; u < 4; u++) ((float4*)Wt)[t + u * 256] = pre[u];
    __syncthreads();

    #pragma unroll
    for (int kt = 0; kt < C / KT; kt++) {
        if (kt + 1 < C / KT) {
            const float4* src = (const float4*)(W + (kt + 1) * KT * C);
            #pragma unroll
            for (int u = 0; u < 4; u++) pre[u] = src[t + u * 256];
        }
        int cb = kt * KT;
        #pragma unroll 8
        for (int c = 0; c < KT; c++) {
            float4 w = *(const float4*)(&Wt[c][jc]);
            float a0 = In[rr][cb + c];
            float a1 = In[rr + 1][cb + c];
            acc[0][0] += a0 * w.x; acc[0][1] += a0 * w.y;
            acc[0][2] += a0 * w.z; acc[0][3] += a0 * w.w;
            acc[1][0] += a1 * w.x; acc[1][1] += a1 * w.y;
            acc[1][2] += a1 * w.z; acc[1][3] += a1 * w.w;
        }
        __syncthreads();                       // everyone done reading Wt
        if (kt + 1 < C / KT) {
            #pragma unroll
            for (int u = 0; u < 4; u++) ((float4*)Wt)[t + u * 256] = pre[u];
            __syncthreads();                   // Wt refilled
        }
    }
}

// ---------------------------------------------------------------------------
// Kernel 1 (fused front): LN(x), LN(s)*sw; a = sigmoid(sn@Wg+bg)*lnx + sn@Ws;
// q = a@Wq+bq; k = a@Wk; v = a@Wv.   128 blocks x 256 threads, 16 rows each.
// ---------------------------------------------------------------------------
__global__ void __launch_bounds__(256)
fused_front_kernel(const float* __restrict__ x,
                   const float* __restrict__ s,
                   const float* __restrict__ sw,
                   const float* __restrict__ Wg,
                   const float* __restrict__ bg,
                   const float* __restrict__ Ws,
                   const float* __restrict__ Wq,
                   const float* __restrict__ bq,
                   const float* __restrict__ Wk,
                   const float* __restrict__ Wv) {
    int row0 = blockIdx.x * TR;
    int t = threadIdx.x;
    int w = t >> 5, l = t & 31;
    __shared__ float Sn[TR][C];
    __shared__ float Lx[TR][C];
    __shared__ float As[TR][C];
    __shared__ float Wt[KT][C];

    // --- LN phase: 8 warps, 2 rows each ---
    #pragma unroll
    for (int rr_ = 0; rr_ < 2; rr_++) {
        int r = w * 2 + rr_;
        float4 xv = ((const float4*)(x + (size_t)(row0 + r) * C))[l];
        float4 sv = ((const float4*)(s + (size_t)(row0 + r) * C))[l];
        float sx  = xv.x + xv.y + xv.z + xv.w;
        float sxx = xv.x*xv.x + xv.y*xv.y + xv.z*xv.z + xv.w*xv.w;
        float ss  = sv.x + sv.y + sv.z + sv.w;
        float sss = sv.x*sv.x + sv.y*sv.y + sv.z*sv.z + sv.w*sv.w;
        #pragma unroll
        for (int o = 16; o > 0; o >>= 1) {
            sx  += __shfl_xor_sync(0xffffffffu, sx,  o);
            sxx += __shfl_xor_sync(0xffffffffu, sxx, o);
            ss  += __shfl_xor_sync(0xffffffffu, ss,  o);
            sss += __shfl_xor_sync(0xffffffffu, sss, o);
        }
        float mx = sx * (1.0f / C);
        float vx = sxx * (1.0f / C) - mx * mx;
        float ms = ss * (1.0f / C);
        float vs = sss * (1.0f / C) - ms * ms;
        float rx = rsqrtf(vx + 1e-5f);
        float rs = rsqrtf(vs + 1e-5f);
        int col = l * 4;
        float4 swv = ((const float4*)sw)[l];
        Lx[r][col + 0] = (xv.x - mx) * rx;
        Lx[r][col + 1] = (xv.y - mx) * rx;
        Lx[r][col + 2] = (xv.z - mx) * rx;
        Lx[r][col + 3] = (xv.w - mx) * rx;
        Sn[r][col + 0] = (sv.x - ms) * rs * swv.x;
        Sn[r][col + 1] = (sv.y - ms) * rs * swv.y;
        Sn[r][col + 2] = (sv.z - ms) * rs * swv.z;
        Sn[r][col + 3] = (sv.w - ms) * rs * swv.w;
    }
    // (Sn/Lx ordering handled by the first gemm_pass prologue sync)

    int jc = (t & 31) * 4;
    int rr = (t >> 5) * 2;

    // pass 1: gate = Sn@Wg   (held in regs)
    float gacc[2][4] = {};
    gemm_pass(Sn, Wg, Wt, gacc, rr, jc, t);
    // pass 2: skip = Sn@Ws ; As = sigmoid(gate+bg)*Lx + skip
    float sacc[2][4] = {};
    gemm_pass(Sn, Ws, Wt, sacc, rr, jc, t);
    #pragma unroll
    for (int r = 0; r < 2; r++)
        #pragma unroll
        for (int u = 0; u < 4; u++)
            As[rr + r][jc + u] =
                sigmoidf_(gacc[r][u] + bg[jc + u]) * Lx[rr + r][jc + u] + sacc[r][u];

    // pass 3/4/5: q, k, v
    {
        float acc[2][4] = {};
        gemm_pass(As, Wq, Wt, acc, rr, jc, t);
        #pragma unroll
        for (int r = 0; r < 2; r++)
            #pragma unroll
            for (int u = 0; u < 4; u++)
                g_q[(row0 + rr + r) * C + jc + u] = acc[r][u] + bq[jc + u];
    }
    {
        float acc[2][4] = {};
        gemm_pass(As, Wk, Wt, acc, rr, jc, t);
        #pragma unroll
        for (int r = 0; r < 2; r++)
            #pragma unroll
            for (int u = 0; u < 4; u++)
                g_k[(row0 + rr + r) * C + jc + u] = acc[r][u];
    }
    {
        float acc[2][4] = {};
        gemm_pass(As, Wv, Wt, acc, rr, jc, t);
        #pragma unroll
        for (int r = 0; r < 2; r++)
            #pragma unroll
            for (int u = 0; u < 4; u++)
                g_v[(row0 + rr + r) * C + jc + u] = acc[r][u];
    }
}

// ---------------------------------------------------------------------------
// Kernel 2: windowed pair bias.  Reads only the used 1/16 of `pair` (16 MB).
// ---------------------------------------------------------------------------
__global__ void pbias_kernel(const float* __restrict__ pair,
                             const float* __restrict__ lnw,
                             const float* __restrict__ lnb,
                             const float* __restrict__ proj) {
    int gid = blockIdx.x * blockDim.x + threadIdx.x;  // 0 .. 262143
    int i = gid >> 12;
    int q = (gid >> 7) & 31;
    int k = gid & 127;
    int n = i * NQ + q;
    int m = i * NQ - PADW + k;

    float b[8] = {0, 0, 0, 0, 0, 0, 0, 0};
    if (m >= 0 && m < N_TOK) {
        const float4* p = (const float4*)(pair + ((size_t)n * N_TOK + m) * CPD);
        float4 v0 = p[0], v1 = p[1], v2 = p[2], v3 = p[3];
        float vals[16] = {v0.x, v0.y, v0.z, v0.w, v1.x, v1.y, v1.z, v1.w,
                          v2.x, v2.y, v2.z, v2.w, v3.x, v3.y, v3.z, v3.w};
        float sum = 0.f;
        #pragma unroll
        for (int c = 0; c < 16; c++) sum += vals[c];
        float mean = sum * (1.0f / 16.0f);
        float var = 0.f;
        #pragma unroll
        for (int c = 0; c < 16; c++) {
            float d = vals[c] - mean;
            var += d * d;
        }
        var *= (1.0f / 16.0f);
        float rs = rsqrtf(var + 1e-5f);
        #pragma unroll
        for (int c = 0; c < 16; c++) {
            float y = (vals[c] - mean) * rs * lnw[c] + lnb[c];
            #pragma unroll
            for (int h = 0; h < 8; h++) b[h] += y * proj[c * 8 + h];
        }
    }
    #pragma unroll
    for (int h = 0; h < 8; h++)
        g_pb[((i * H + h) * NQ + q) * NK + k] = b[h];
}

// ---------------------------------------------------------------------------
// Kernel 3: local window attention.  1 block per (head, window) = 512 blocks.
// ---------------------------------------------------------------------------
__global__ void attn_kernel() {
    int h = blockIdx.x;
    int i = blockIdx.y;
    int t = threadIdx.x;       // 256
    __shared__ float Ks[NK * 17];
    __shared__ float Vs[NK * 17];
    __shared__ float Qs[NQ * 17];

    int qi = t >> 3;
    int kb = t & 7;
    int base_m = i * NQ - PADW;

    for (int idx = t; idx < NK * HD; idx += 256) {
        int kk = idx >> 4, d = idx & 15;
        int m = base_m + kk;
        float kvv = 0.f, vvv = 0.f;
        if (m >= 0 && m < N_TOK) {
            kvv = g_k[m * C + h * HD + d];
            vvv = g_v[m * C + h * HD + d];
        }
        Ks[kk * 17 + d] = kvv;
        Vs[kk * 17 + d] = vvv;
    }
    for (int idx = t; idx < NQ * HD; idx += 256) {
        int qq = idx >> 4, d = idx & 15;
        Qs[qq * 17 + d] = g_q[(i * NQ + qq) * C + h * HD + d];
    }
    __syncthreads();

    float qr[16];
    #pragma unroll
    for (int d = 0; d < 16; d++) qr[d] = Qs[qi * 17 + d];

    const float* bp = g_pb + ((i * H + h) * NQ + qi) * NK;

    float lg[16];
    #pragma unroll
    for (int j = 0; j < 16; j++) {
        int k = kb + 8 * j;
        float acc = 0.f;
        #pragma unroll
        for (int d = 0; d < 16; d++) acc += qr[d] * Ks[k * 17 + d];
        lg[j] = acc * 0.25f + bp[k];
    }

    float mx = lg[0];
    #pragma unroll
    for (int j = 1; j < 16; j++) mx = fmaxf(mx, lg[j]);
    #pragma unroll
    for (int o = 4; o > 0; o >>= 1)
        mx = fmaxf(mx, __shfl_xor_sync(0xffffffffu, mx, o));

    float sm = 0.f;
    #pragma unroll
    for (int j = 0; j < 16; j++) {
        lg[j] = __expf(lg[j] - mx);
        sm += lg[j];
    }
    #pragma unroll
    for (int o = 4; o > 0; o >>= 1)
        sm += __shfl_xor_sync(0xffffffffu, sm, o);
    float inv = 1.0f / sm;

    float po[16] = {};
    #pragma unroll
    for (int j = 0; j < 16; j++) {
        int k = kb + 8 * j;
        float p = lg[j] * inv;
        #pragma unroll
        for (int d = 0; d < 16; d++) po[d] += p * Vs[k * 17 + d];
    }
    #pragma unroll
    for (int o = 4; o > 0; o >>= 1) {
        #pragma unroll
        for (int d = 0; d < 16; d++)
            po[d] += __shfl_xor_sync(0xffffffffu, po[d], o);
    }
    int n = i * NQ + qi;
    g_o[n * C + h * HD + 2 * kb]     = po[2 * kb];
    g_o[n * C + h * HD + 2 * kb + 1] = po[2 * kb + 1];
}

// ---------------------------------------------------------------------------
// Kernel 4: tail chain: g = sigmoid(o@Wg)*o ; t1 = g@Wp ;
//           out = sigmoid(t1@Wo + bo)*t1.   128 blocks x 256 threads.
// ---------------------------------------------------------------------------
__global__ void __launch_bounds__(256)
tail_kernel(const float* __restrict__ Wg,
            const float* __restrict__ Wp,
            const float* __restrict__ Wo,
            const float* __restrict__ bo,
            float* __restrict__ out) {
    int row0 = blockIdx.x * TR;
    int t = threadIdx.x;
    __shared__ float A[TR][C];
    __shared__ float Bm[TR][C];
    __shared__ float Wt[KT][C];
    for (int idx = t; idx < TR * C; idx += 256)
        A[idx >> 7][idx & 127] = g_o[row0 * C + idx];

    int jc = (t & 31) * 4;
    int rr = (t >> 5) * 2;

    // phase 1: Bm = sigmoid(A@Wg) * A
    {
        float acc[2][4] = {};
        gemm_pass(A, Wg, Wt, acc, rr, jc, t);
        #pragma unroll
        for (int r = 0; r < 2; r++)
            #pragma unroll
            for (int u = 0; u < 4; u++)
                Bm[rr + r][jc + u] = sigmoidf_(acc[r][u]) * A[rr + r][jc + u];
    }
    // phase 2: t1 = Bm@Wp  -> overwrite A
    {
        float acc[2][4] = {};
        gemm_pass(Bm, Wp, Wt, acc, rr, jc, t);
        #pragma unroll
        for (int r = 0; r < 2; r++)
            #pragma unroll
            for (int u = 0; u < 4; u++)
                A[rr + r][jc + u] = acc[r][u];
    }
    // phase 3: out = sigmoid(A@Wo + bo) * A
    {
        float acc[2][4] = {};
        gemm_pass(A, Wo, Wt, acc, rr, jc, t);
        #pragma unroll
        for (int r = 0; r < 2; r++)
            #pragma unroll
            for (int u = 0; u < 4; u++) {
                float tv = acc[r][u] + bo[jc + u];
                out[(row0 + rr + r) * C + jc + u] = sigmoidf_(tv) * A[rr + r][jc + u];
            }
    }
}

// ---------------------------------------------------------------------------
extern "C" void kernel_launch(void* const* d_in, const int* in_sizes, int n_in,
                              void* d_out, int out_size) {
    const float* x        = (const float*)d_in[0];
    const float* s        = (const float*)d_in[1];
    const float* pair     = (const float*)d_in[2];
    const float* adaln_sw = (const float*)d_in[3];
    const float* adaln_gw = (const float*)d_in[4];
    const float* adaln_gb = (const float*)d_in[5];
    const float* adaln_kw = (const float*)d_in[6];
    const float* q_w      = (const float*)d_in[7];
    const float* q_b      = (const float*)d_in[8];
    const float* k_w      = (const float*)d_in[9];
    const float* v_w      = (const float*)d_in[10];
    const float* p_lnw    = (const float*)d_in[11];
    const float* p_lnb    = (const float*)d_in[12];
    const float* p_proj   = (const float*)d_in[13];
    const float* gate_w   = (const float*)d_in[14];
    const float* proj_w   = (const float*)d_in[15];
    const float* out_w    = (const float*)d_in[16];
    const float* out_b    = (const float*)d_in[17];
    float* out = (float*)d_out;

    fused_front_kernel<<<N_TOK / TR, 256>>>(x, s, adaln_sw,
                                            adaln_gw, adaln_gb, adaln_kw,
                                            q_w, q_b, k_w, v_w);
    pbias_kernel<<<(NB * NQ * NK) / 256, 256>>>(pair, p_lnw, p_lnb, p_proj);
    attn_kernel <<<dim3(H, NB), 256>>>();
    tail_kernel <<<N_TOK / TR, 256>>>(gate_w, proj_w, out_w, out_b, out);
}

// round 10
// speedup vs baseline: 1.7477x; 1.5412x over previous
#include <cuda_runtime.h>
#include <math.h>

#define N_TOK 2048
#define C     128
#define CPD   16
#define H     8
#define HD    16
#define NQ    32
#define NK    128
#define NB    64
#define PADW  48
#define TR    8    // rows per GEMM block
#define KT    32   // k-tile rows per smem buffer

// Scratch (device globals — no allocations allowed)
__device__ float g_q  [N_TOK * C];
__device__ float g_k  [N_TOK * C];
__device__ float g_v  [N_TOK * C];
__device__ float g_o  [N_TOK * C];
__device__ float g_pb [NB * H * NQ * NK];   // pair bias, layout [i][h][q][k]

__device__ __forceinline__ float sigmoidf_(float x) {
    return 1.0f / (1.0f + __expf(-x));
}

// ---------------------------------------------------------------------------
// One GEMM pass: acc[2][4] += In[rr..rr+1][:] @ W[:, jc..jc+3]
// W (128x128 row-major) streamed through a DOUBLE-BUFFERED 32x128 smem tile:
// exactly one __syncthreads() per k-tile; next tile's LDG/STS overlaps compute.
// 128 threads. Prologue sync also orders any prior smem writes to In.
// ---------------------------------------------------------------------------
__device__ __forceinline__ void gemm_pass(const float (*In)[C],
                                          const float* __restrict__ W,
                                          float (*Wt)[KT][C],   // [2][KT][C]
                                          float acc[2][4],
                                          int rr, int jc, int t) {
    const float4* srcv = (const float4*)W;      // 4096 float4; tile = 1024
    float4 tmp[8];
    #pragma unroll
    for (int u = 0; u < 8; u++) tmp[u] = srcv[t + u * 128];
    #pragma unroll
    for (int u = 0; u < 8; u++) ((float4*)Wt[0])[t + u * 128] = tmp[u];
    __syncthreads();

    #pragma unroll
    for (int kt = 0; kt < C / KT; kt++) {
        int cur = kt & 1;
        if (kt + 1 < C / KT) {
            #pragma unroll
            for (int u = 0; u < 8; u++)
                tmp[u] = srcv[(kt + 1) * 1024 + t + u * 128];
            #pragma unroll
            for (int u = 0; u < 8; u++)
                ((float4*)Wt[cur ^ 1])[t + u * 128] = tmp[u];
        }
        #pragma unroll
        for (int c4 = 0; c4 < KT / 4; c4++) {
            float4 a0 = *(const float4*)(&In[rr][kt * KT + c4 * 4]);
            float4 a1 = *(const float4*)(&In[rr + 1][kt * KT + c4 * 4]);
            float av0[4] = {a0.x, a0.y, a0.z, a0.w};
            float av1[4] = {a1.x, a1.y, a1.z, a1.w};
            #pragma unroll
            for (int cc = 0; cc < 4; cc++) {
                float4 w = *(const float4*)(&Wt[cur][c4 * 4 + cc][jc]);
                acc[0][0] += av0[cc] * w.x; acc[0][1] += av0[cc] * w.y;
                acc[0][2] += av0[cc] * w.z; acc[0][3] += av0[cc] * w.w;
                acc[1][0] += av1[cc] * w.x; acc[1][1] += av1[cc] * w.y;
                acc[1][2] += av1[cc] * w.z; acc[1][3] += av1[cc] * w.w;
            }
        }
        __syncthreads();   // readers done with cur; writers done with cur^1
    }
}

// ---------------------------------------------------------------------------
// Kernel 1 (fused front): LN(x), LN(s)*sw; a = sigmoid(sn@Wg+bg)*lnx + sn@Ws;
// q = a@Wq+bq; k = a@Wk; v = a@Wv.   256 blocks x 128 threads, 8 rows each.
// ---------------------------------------------------------------------------
__global__ void __launch_bounds__(128)
fused_front_kernel(const float* __restrict__ x,
                   const float* __restrict__ s,
                   const float* __restrict__ sw,
                   const float* __restrict__ Wg,
                   const float* __restrict__ bg,
                   const float* __restrict__ Ws,
                   const float* __restrict__ Wq,
                   const float* __restrict__ bq,
                   const float* __restrict__ Wk,
                   const float* __restrict__ Wv) {
    int row0 = blockIdx.x * TR;
    int t = threadIdx.x;            // 128
    int w = t >> 5, l = t & 31;
    __shared__ float Sn[TR][C];
    __shared__ float Lx[TR][C];
    __shared__ float As[TR][C];
    __shared__ float Wt[2][KT][C];

    // --- LN phase: 4 warps, 2 rows each ---
    #pragma unroll
    for (int rr_ = 0; rr_ < 2; rr_++) {
        int r = w * 2 + rr_;
        float4 xv = ((const float4*)(x + (size_t)(row0 + r) * C))[l];
        float4 sv = ((const float4*)(s + (size_t)(row0 + r) * C))[l];
        float sx  = xv.x + xv.y + xv.z + xv.w;
        float sxx = xv.x*xv.x + xv.y*xv.y + xv.z*xv.z + xv.w*xv.w;
        float ss  = sv.x + sv.y + sv.z + sv.w;
        float sss = sv.x*sv.x + sv.y*sv.y + sv.z*sv.z + sv.w*sv.w;
        #pragma unroll
        for (int o = 16; o > 0; o >>= 1) {
            sx  += __shfl_xor_sync(0xffffffffu, sx,  o);
            sxx += __shfl_xor_sync(0xffffffffu, sxx, o);
            ss  += __shfl_xor_sync(0xffffffffu, ss,  o);
            sss += __shfl_xor_sync(0xffffffffu, sss, o);
        }
        float mx = sx * (1.0f / C);
        float vx = sxx * (1.0f / C) - mx * mx;
        float ms = ss * (1.0f / C);
        float vs = sss * (1.0f / C) - ms * ms;
        float rx = rsqrtf(vx + 1e-5f);
        float rs = rsqrtf(vs + 1e-5f);
        int col = l * 4;
        float4 swv = ((const float4*)sw)[l];
        Lx[r][col + 0] = (xv.x - mx) * rx;
        Lx[r][col + 1] = (xv.y - mx) * rx;
        Lx[r][col + 2] = (xv.z - mx) * rx;
        Lx[r][col + 3] = (xv.w - mx) * rx;
        Sn[r][col + 0] = (sv.x - ms) * rs * swv.x;
        Sn[r][col + 1] = (sv.y - ms) * rs * swv.y;
        Sn[r][col + 2] = (sv.z - ms) * rs * swv.z;
        Sn[r][col + 3] = (sv.w - ms) * rs * swv.w;
    }
    // (ordering handled by first gemm_pass prologue sync)

    int jc = (t & 31) * 4;
    int rr = (t >> 5) * 2;

    // pass 1: gate = Sn@Wg  (held in regs)
    float gacc[2][4] = {};
    gemm_pass(Sn, Wg, Wt, gacc, rr, jc, t);
    // pass 2: skip = Sn@Ws ; As = sigmoid(gate+bg)*Lx + skip
    float sacc[2][4] = {};
    gemm_pass(Sn, Ws, Wt, sacc, rr, jc, t);
    #pragma unroll
    for (int r = 0; r < 2; r++)
        #pragma unroll
        for (int u = 0; u < 4; u++)
            As[rr + r][jc + u] =
                sigmoidf_(gacc[r][u] + bg[jc + u]) * Lx[rr + r][jc + u] + sacc[r][u];

    // pass 3/4/5: q, k, v
    {
        float acc[2][4] = {};
        gemm_pass(As, Wq, Wt, acc, rr, jc, t);
        #pragma unroll
        for (int r = 0; r < 2; r++)
            #pragma unroll
            for (int u = 0; u < 4; u++)
                g_q[(row0 + rr + r) * C + jc + u] = acc[r][u] + bq[jc + u];
    }
    {
        float acc[2][4] = {};
        gemm_pass(As, Wk, Wt, acc, rr, jc, t);
        #pragma unroll
        for (int r = 0; r < 2; r++)
            #pragma unroll
            for (int u = 0; u < 4; u++)
                g_k[(row0 + rr + r) * C + jc + u] = acc[r][u];
    }
    {
        float acc[2][4] = {};
        gemm_pass(As, Wv, Wt, acc, rr, jc, t);
        #pragma unroll
        for (int r = 0; r < 2; r++)
            #pragma unroll
            for (int u = 0; u < 4; u++)
                g_v[(row0 + rr + r) * C + jc + u] = acc[r][u];
    }
}

// ---------------------------------------------------------------------------
// Kernel 2: windowed pair bias.  Reads only the used 1/16 of `pair` (16 MB).
// ---------------------------------------------------------------------------
__global__ void pbias_kernel(const float* __restrict__ pair,
                             const float* __restrict__ lnw,
                             const float* __restrict__ lnb,
                             const float* __restrict__ proj) {
    int gid = blockIdx.x * blockDim.x + threadIdx.x;  // 0 .. 262143
    int i = gid >> 12;
    int q = (gid >> 7) & 31;
    int k = gid & 127;
    int n = i * NQ + q;
    int m = i * NQ - PADW + k;

    float b[8] = {0, 0, 0, 0, 0, 0, 0, 0};
    if (m >= 0 && m < N_TOK) {
        const float4* p = (const float4*)(pair + ((size_t)n * N_TOK + m) * CPD);
        float4 v0 = p[0], v1 = p[1], v2 = p[2], v3 = p[3];
        float vals[16] = {v0.x, v0.y, v0.z, v0.w, v1.x, v1.y, v1.z, v1.w,
                          v2.x, v2.y, v2.z, v2.w, v3.x, v3.y, v3.z, v3.w};
        float sum = 0.f;
        #pragma unroll
        for (int c = 0; c < 16; c++) sum += vals[c];
        float mean = sum * (1.0f / 16.0f);
        float var = 0.f;
        #pragma unroll
        for (int c = 0; c < 16; c++) {
            float d = vals[c] - mean;
            var += d * d;
        }
        var *= (1.0f / 16.0f);
        float rs = rsqrtf(var + 1e-5f);
        #pragma unroll
        for (int c = 0; c < 16; c++) {
            float y = (vals[c] - mean) * rs * lnw[c] + lnb[c];
            #pragma unroll
            for (int h = 0; h < 8; h++) b[h] += y * proj[c * 8 + h];
        }
    }
    #pragma unroll
    for (int h = 0; h < 8; h++)
        g_pb[((i * H + h) * NQ + q) * NK + k] = b[h];
}

// ---------------------------------------------------------------------------
// Kernel 3: local window attention.  1 block per (head, window) = 512 blocks.
// ---------------------------------------------------------------------------
__global__ void attn_kernel() {
    int h = blockIdx.x;
    int i = blockIdx.y;
    int t = threadIdx.x;       // 256
    __shared__ float Ks[NK * 17];
    __shared__ float Vs[NK * 17];
    __shared__ float Qs[NQ * 17];

    int qi = t >> 3;
    int kb = t & 7;
    int base_m = i * NQ - PADW;

    for (int idx = t; idx < NK * HD; idx += 256) {
        int kk = idx >> 4, d = idx & 15;
        int m = base_m + kk;
        float kvv = 0.f, vvv = 0.f;
        if (m >= 0 && m < N_TOK) {
            kvv = g_k[m * C + h * HD + d];
            vvv = g_v[m * C + h * HD + d];
        }
        Ks[kk * 17 + d] = kvv;
        Vs[kk * 17 + d] = vvv;
    }
    for (int idx = t; idx < NQ * HD; idx += 256) {
        int qq = idx >> 4, d = idx & 15;
        Qs[qq * 17 + d] = g_q[(i * NQ + qq) * C + h * HD + d];
    }
    __syncthreads();

    float qr[16];
    #pragma unroll
    for (int d = 0; d < 16; d++) qr[d] = Qs[qi * 17 + d];

    const float* bp = g_pb + ((i * H + h) * NQ + qi) * NK;

    float lg[16];
    #pragma unroll
    for (int j = 0; j < 16; j++) {
        int k = kb + 8 * j;
        float acc = 0.f;
        #pragma unroll
        for (int d = 0; d < 16; d++) acc += qr[d] * Ks[k * 17 + d];
        lg[j] = acc * 0.25f + bp[k];
    }

    float mx = lg[0];
    #pragma unroll
    for (int j = 1; j < 16; j++) mx = fmaxf(mx, lg[j]);
    #pragma unroll
    for (int o = 4; o > 0; o >>= 1)
        mx = fmaxf(mx, __shfl_xor_sync(0xffffffffu, mx, o));

    float sm = 0.f;
    #pragma unroll
    for (int j = 0; j < 16; j++) {
        lg[j] = __expf(lg[j] - mx);
        sm += lg[j];
    }
    #pragma unroll
    for (int o = 4; o > 0; o >>= 1)
        sm += __shfl_xor_sync(0xffffffffu, sm, o);
    float inv = 1.0f / sm;

    float po[16] = {};
    #pragma unroll
    for (int j = 0; j < 16; j++) {
        int k = kb + 8 * j;
        float p = lg[j] * inv;
        #pragma unroll
        for (int d = 0; d < 16; d++) po[d] += p * Vs[k * 17 + d];
    }
    #pragma unroll
    for (int o = 4; o > 0; o >>= 1) {
        #pragma unroll
        for (int d = 0; d < 16; d++)
            po[d] += __shfl_xor_sync(0xffffffffu, po[d], o);
    }
    int n = i * NQ + qi;
    g_o[n * C + h * HD + 2 * kb]     = po[2 * kb];
    g_o[n * C + h * HD + 2 * kb + 1] = po[2 * kb + 1];
}

// ---------------------------------------------------------------------------
// Kernel 4: tail chain: g = sigmoid(o@Wg)*o ; t1 = g@Wp ;
//           out = sigmoid(t1@Wo + bo)*t1.   256 blocks x 128 threads.
// ---------------------------------------------------------------------------
__global__ void __launch_bounds__(128)
tail_kernel(const float* __restrict__ Wg,
            const float* __restrict__ Wp,
            const float* __restrict__ Wo,
            const float* __restrict__ bo,
            float* __restrict__ out) {
    int row0 = blockIdx.x * TR;
    int t = threadIdx.x;
    __shared__ float A[TR][C];
    __shared__ float Bm[TR][C];
    __shared__ float Wt[2][KT][C];
    #pragma unroll
    for (int u = 0; u < 2; u++)
        ((float4*)A)[t + u * 128] = ((const float4*)(g_o + (size_t)row0 * C))[t + u * 128];

    int jc = (t & 31) * 4;
    int rr = (t >> 5) * 2;

    // phase 1: Bm = sigmoid(A@Wg) * A
    {
        float acc[2][4] = {};
        gemm_pass(A, Wg, Wt, acc, rr, jc, t);
        #pragma unroll
        for (int r = 0; r < 2; r++)
            #pragma unroll
            for (int u = 0; u < 4; u++)
                Bm[rr + r][jc + u] = sigmoidf_(acc[r][u]) * A[rr + r][jc + u];
    }
    // phase 2: t1 = Bm@Wp  (A reads in phase 1 epilogue done before the
    // prologue sync of this pass; A overwritten only after pass returns)
    float t1[2][4] = {};
    gemm_pass(Bm, Wp, Wt, t1, rr, jc, t);
    #pragma unroll
    for (int r = 0; r < 2; r++)
        #pragma unroll
        for (int u = 0; u < 4; u++)
            A[rr + r][jc + u] = t1[r][u];

    // phase 3: out = sigmoid(A@Wo + bo) * A
    {
        float acc[2][4] = {};
        gemm_pass(A, Wo, Wt, acc, rr, jc, t);
        #pragma unroll
        for (int r = 0; r < 2; r++)
            #pragma unroll
            for (int u = 0; u < 4; u++) {
                float tv = acc[r][u] + bo[jc + u];
                out[(row0 + rr + r) * C + jc + u] = sigmoidf_(tv) * t1[r][u];
            }
    }
}

// ---------------------------------------------------------------------------
extern "C" void kernel_launch(void* const* d_in, const int* in_sizes, int n_in,
                              void* d_out, int out_size) {
    const float* x        = (const float*)d_in[0];
    const float* s        = (const float*)d_in[1];
    const float* pair     = (const float*)d_in[2];
    const float* adaln_sw = (const float*)d_in[3];
    const float* adaln_gw = (const float*)d_in[4];
    const float* adaln_gb = (const float*)d_in[5];
    const float* adaln_kw = (const float*)d_in[6];
    const float* q_w      = (const float*)d_in[7];
    const float* q_b      = (const float*)d_in[8];
    const float* k_w      = (const float*)d_in[9];
    const float* v_w      = (const float*)d_in[10];
    const float* p_lnw    = (const float*)d_in[11];
    const float* p_lnb    = (const float*)d_in[12];
    const float* p_proj   = (const float*)d_in[13];
    const float* gate_w   = (const float*)d_in[14];
    const float* proj_w   = (const float*)d_in[15];
    const float* out_w    = (const float*)d_in[16];
    const float* out_b    = (const float*)d_in[17];
    float* out = (float*)d_out;

    fused_front_kernel<<<N_TOK / TR, 128>>>(x, s, adaln_sw,
                                            adaln_gw, adaln_gb, adaln_kw,
                                            q_w, q_b, k_w, v_w);
    pbias_kernel<<<(NB * NQ * NK) / 256, 256>>>(pair, p_lnw, p_lnb, p_proj);
    attn_kernel <<<dim3(H, NB), 256>>>();
    tail_kernel <<<N_TOK / TR, 128>>>(gate_w, proj_w, out_w, out_b, out);
}